// round 8
// baseline (speedup 1.0000x reference)
#include <cuda_runtime.h>
#include <cuda_fp16.h>
#include <cstdint>

#define B_   32
#define C_   128
#define L_   4096
#define P_   100
#define Q_   20
#define LG   256            // l per block
#define NLG  (L_ / LG)      // 16
#define CL   64             // chunk l
#define NCH  4              // chunks per block
#define NG   32             // store groups per (b,p): 16 lg x 2

#define STG_W    68                      // stage row stride in words (64 + 4 pad)
#define STG_B    (STG_W * 4)             // 272 B
#define STG_SZ   (C_ * STG_B)            // 34816 B
#define SM_STG0  0
#define SM_STG1  STG_SZ
#define SM_TILE  (2 * STG_SZ)            // fp16 tile: 128 rows x 128 B = 16384
#define SM_TBL   (SM_TILE + C_ * 128)    // 86016
#define SM_TOTAL (SM_TBL + 441 * 32)     // 100128

// chunk scratch: [b][p(128)][w5(5)][g(32)] packed byte counters
__device__ unsigned g_chunk[B_ * 128 * 5 * NG];

__device__ __forceinline__ unsigned smem_u32(const void* p) {
    unsigned a;
    asm("{ .reg .u64 t; cvta.to.shared.u64 t, %1; cvt.u32.u64 %0, t; }" : "=r"(a) : "l"(p));
    return a;
}
#define CP_ASYNC16(sa, ga) \
    asm volatile("cp.async.cg.shared.global [%0], [%1], 16;" :: "r"(sa), "l"(ga))
#define CP_COMMIT() asm volatile("cp.async.commit_group;" ::: "memory")
#define CP_WAIT1()  asm volatile("cp.async.wait_group 1;" ::: "memory")
#define CP_WAIT0()  asm volatile("cp.async.wait_group 0;" ::: "memory")

#define LDSM_T(r0, r1, r2, r3, a) \
    asm volatile("ldmatrix.sync.aligned.m8n8.x4.trans.shared.b16 {%0,%1,%2,%3}, [%4];" \
                 : "=r"(r0), "=r"(r1), "=r"(r2), "=r"(r3) : "r"(a))
#define MMA_F16(Cv, Af, b0_, b1_) \
    asm volatile("mma.sync.aligned.m16n8k16.row.col.f32.f16.f16.f32 " \
                 "{%0,%1,%2,%3}, {%4,%5,%6,%7}, {%8,%9}, {%0,%1,%2,%3};" \
                 : "+f"((Cv)[0]), "+f"((Cv)[1]), "+f"((Cv)[2]), "+f"((Cv)[3]) \
                 : "r"((Af).x), "r"((Af).y), "r"((Af).z), "r"((Af).w), "r"(b0_), "r"(b1_))

__device__ __forceinline__ unsigned bin_of(float a, float s, float bc) {
    float g = fminf(fmaxf(fmaf(a, s, bc), -0.5f), 19.99f);
    return __float_as_uint(__fadd_rn(g, 12582912.0f)) & 63u;
}
__device__ __forceinline__ unsigned h2bits(__half2 h) { return *(unsigned*)&h; }

// ---------------------------------------------------------------------------
extern __shared__ __align__(16) char smem[];

__global__ __launch_bounds__(256, 2)
void radon_hmma(const float* __restrict__ X,
                const float* __restrict__ W,
                const float* __restrict__ minv,
                const float* __restrict__ maxv,
                int blkbase) {
    const int blk = blkbase + blockIdx.x;
    const int tid = threadIdx.x, w = tid >> 5, lane = tid & 31;
    const int b = blk >> 4, lg = blk & 15;
    const unsigned sb = smem_u32(smem);
    unsigned* tbl = (unsigned*)(smem + SM_TBL);

    // pair table: tbl[j1*21+j2][w5] bytes(q=4*w5+b4) = (q>=j1)+(q>=j2); stride 8
    for (int i = tid; i < 441 * 8; i += 256) {
        int row = i >> 3, w5 = i & 7;
        int j1 = row / 21, j2 = row % 21;
        unsigned v = 0;
        if (w5 < 5) {
#pragma unroll
            for (int b4 = 0; b4 < 4; b4++) {
                int q = 4 * w5 + b4;
                if (q < Q_) v |= (unsigned)((q >= j1) + (q >= j2)) << (8 * b4);
            }
        }
        tbl[i] = v;
    }

    const float* Xb = X + (size_t)b * C_ * L_ + lg * LG;

    // prologue: stage chunk 0 (overlaps A-frag LDGs below)
    {
        const float* Xc = Xb;  // chunk 0
#pragma unroll
        for (int pas = 0; pas < 8; pas++) {
            int c = pas * 16 + (tid >> 4), l16 = tid & 15;
            unsigned sa = sb + SM_STG0 + c * STG_B + l16 * 16;
            CP_ASYNC16(sa, (const char*)(Xc + (size_t)c * L_) + l16 * 16);
        }
        CP_COMMIT();
    }

    // A fragments from W (single rn fp16)
    const int r0 = w * 16 + (lane >> 2);
    const int r1 = r0 + 8;
    const int kp0 = 2 * (lane & 3);
    uint4 Ahi[8];
#pragma unroll
    for (int s = 0; s < 8; s++) {
        int kp = s * 16 + kp0;
        float2 a00 = (r0 < P_) ? *(const float2*)(W + r0 * C_ + kp)     : make_float2(0.f, 0.f);
        float2 a10 = (r1 < P_) ? *(const float2*)(W + r1 * C_ + kp)     : make_float2(0.f, 0.f);
        float2 a01 = (r0 < P_) ? *(const float2*)(W + r0 * C_ + kp + 8) : make_float2(0.f, 0.f);
        float2 a11 = (r1 < P_) ? *(const float2*)(W + r1 * C_ + kp + 8) : make_float2(0.f, 0.f);
        Ahi[s].x = h2bits(__float22half2_rn(a00));
        Ahi[s].y = h2bits(__float22half2_rn(a10));
        Ahi[s].z = h2bits(__float22half2_rn(a01));
        Ahi[s].w = h2bits(__float22half2_rn(a11));
    }

    const int p0 = r0, p1 = r1;
    float s0 = 0.f, c0b = 0.f, s1 = 0.f, c1b = 0.f;
    if (p0 < P_) { float mn = minv[p0]; s0 = 21.0f / (maxv[p0] - mn); c0b = -mn * s0 - 0.5f; }
    if (p1 < P_) { float mn = minv[p1]; s1 = 21.0f / (maxv[p1] - mn); c1b = -mn * s1 - 0.5f; }

    const int rr = lane & 15;
    const unsigned colb0 = (unsigned)((lane >> 4) * 16);
    unsigned acc0[5] = {0, 0, 0, 0, 0}, acc1[5] = {0, 0, 0, 0, 0};

    for (int ch = 0; ch < NCH; ch++) {
        // prefetch next chunk into the other stage buffer (no regs held)
        if (ch + 1 < NCH) {
            const float* Xc = Xb + (ch + 1) * CL;
            unsigned stg = sb + ((ch + 1) & 1 ? SM_STG1 : SM_STG0);
#pragma unroll
            for (int pas = 0; pas < 8; pas++) {
                int c = pas * 16 + (tid >> 4), l16 = tid & 15;
                CP_ASYNC16(stg + c * STG_B + l16 * 16,
                           (const char*)(Xc + (size_t)c * L_) + l16 * 16);
            }
            CP_COMMIT();
            CP_WAIT1();   // chunk ch arrived; ch+1 still in flight
        } else {
            CP_WAIT0();
        }
        __syncthreads();  // stage(ch) visible to all; prior mainloop done (tile free)

        // convert stage(ch) fp32 -> fp16 tile (rows 128 B, 16B XOR swizzle)
        {
            const unsigned stg = sb + ((ch & 1) ? SM_STG1 : SM_STG0);
            int c = tid >> 1, half = tid & 1;
            const unsigned src = stg + c * STG_B + half * 128;
            const unsigned dstrow = sb + SM_TILE + c * 128;
            const unsigned swz = ((unsigned)c & 7u) << 4;
#pragma unroll
            for (int k2 = 0; k2 < 4; k2++) {
                float4 va, vb;
                asm volatile("ld.shared.v4.f32 {%0,%1,%2,%3}, [%4];"
                             : "=f"(va.x), "=f"(va.y), "=f"(va.z), "=f"(va.w)
                             : "r"(src + k2 * 32));
                asm volatile("ld.shared.v4.f32 {%0,%1,%2,%3}, [%4];"
                             : "=f"(vb.x), "=f"(vb.y), "=f"(vb.z), "=f"(vb.w)
                             : "r"(src + k2 * 32 + 16));
                unsigned o0 = h2bits(__float22half2_rn(make_float2(va.x, va.y)));
                unsigned o1 = h2bits(__float22half2_rn(make_float2(va.z, va.w)));
                unsigned o2 = h2bits(__float22half2_rn(make_float2(vb.x, vb.y)));
                unsigned o3 = h2bits(__float22half2_rn(make_float2(vb.z, vb.w)));
                unsigned da = dstrow + (((unsigned)(half * 64 + k2 * 16)) ^ swz);
                asm volatile("st.shared.v4.b32 [%0], {%1,%2,%3,%4};"
                             :: "r"(da), "r"(o0), "r"(o1), "r"(o2), "r"(o3));
            }
        }
        __syncthreads();

        // mainloop: 4 n-pairs of 16 l
        for (int nt2 = 0; nt2 < 4; nt2++) {
            float C0[4] = {0.f, 0.f, 0.f, 0.f}, C1[4] = {0.f, 0.f, 0.f, 0.f};
            const unsigned colb = colb0 + (unsigned)(nt2 * 32);
#pragma unroll
            for (int s = 0; s < 8; s++) {
                int cc = s * 16 + rr;
                unsigned ba = sb + SM_TILE + (unsigned)(cc * 128) +
                              (colb ^ (((unsigned)cc & 7u) << 4));
                unsigned b0, b1, b2, b3;
                LDSM_T(b0, b1, b2, b3, ba);
                MMA_F16(C0, Ahi[s], b0, b1);
                MMA_F16(C1, Ahi[s], b2, b3);
            }
#pragma unroll
            for (int half = 0; half < 2; half++) {
                const float* Cf = half ? C1 : C0;
                unsigned ja = bin_of(Cf[0], s0, c0b) * 21u + bin_of(Cf[1], s0, c0b);
                const uint4 ra = *(const uint4*)(tbl + ja * 8);
                unsigned ra4 = tbl[ja * 8 + 4];
                acc0[0] += ra.x; acc0[1] += ra.y; acc0[2] += ra.z; acc0[3] += ra.w; acc0[4] += ra4;
                unsigned jb = bin_of(Cf[2], s1, c1b) * 21u + bin_of(Cf[3], s1, c1b);
                const uint4 rb = *(const uint4*)(tbl + jb * 8);
                unsigned rb4 = tbl[jb * 8 + 4];
                acc1[0] += rb.x; acc1[1] += rb.y; acc1[2] += rb.z; acc1[3] += rb.w; acc1[4] += rb4;
            }
        }

        if (ch & 1) {  // flush every 2 chunks: pre-shuffle <=32/byte, post <=128
#pragma unroll
            for (int k = 0; k < 5; k++) {
                acc0[k] += __shfl_xor_sync(0xFFFFFFFFu, acc0[k], 1);
                acc0[k] += __shfl_xor_sync(0xFFFFFFFFu, acc0[k], 2);
                acc1[k] += __shfl_xor_sync(0xFFFFFFFFu, acc1[k], 1);
                acc1[k] += __shfl_xor_sync(0xFFFFFFFFu, acc1[k], 2);
            }
            if ((lane & 3) == 0) {
                int g = lg * 2 + (ch >> 1);
                if (p0 < P_) {
                    unsigned* d = g_chunk + ((size_t)(b * 128 + p0) * 5) * NG + g;
#pragma unroll
                    for (int k = 0; k < 5; k++) d[k * NG] = acc0[k];
                }
                if (p1 < P_) {
                    unsigned* d = g_chunk + ((size_t)(b * 128 + p1) * 5) * NG + g;
#pragma unroll
                    for (int k = 0; k < 5; k++) d[k * NG] = acc1[k];
                }
            }
#pragma unroll
            for (int k = 0; k < 5; k++) { acc0[k] = 0; acc1[k] = 0; }
        }
    }
}

// ---------------------------------------------------------------------------
__global__ void finalize_kernel(float* __restrict__ out) {
    int i = blockIdx.x * 256 + threadIdx.x;
    if (i >= B_ * P_ * 5) return;
    int b = i / (P_ * 5), rem = i % (P_ * 5), p = rem / 5, w5 = rem % 5;
    const uint4* src = (const uint4*)(g_chunk + ((size_t)(b * 128 + p) * 5 + w5) * NG);
    unsigned s01 = 0, s23 = 0;
#pragma unroll
    for (int k = 0; k < 8; k++) {
        uint4 v = src[k];
        s01 += (v.x & 0x00FF00FFu) + (v.y & 0x00FF00FFu) + (v.z & 0x00FF00FFu) + (v.w & 0x00FF00FFu);
        s23 += ((v.x >> 8) & 0x00FF00FFu) + ((v.y >> 8) & 0x00FF00FFu) +
               ((v.z >> 8) & 0x00FF00FFu) + ((v.w >> 8) & 0x00FF00FFu);
    }
    float* o = out + (size_t)b * (P_ * Q_) + p * Q_ + 4 * w5;
    const float inv = 1.0f / (float)L_;
    o[0] = (float)(s01 & 0xFFFFu) * inv;
    o[1] = (float)(s23 & 0xFFFFu) * inv;
    o[2] = (float)(s01 >> 16) * inv;
    o[3] = (float)(s23 >> 16) * inv;
}

// ---------------------------------------------------------------------------
extern "C" void kernel_launch(void* const* d_in, const int* in_sizes, int n_in,
                              void* d_out, int out_size) {
    const float* X    = (const float*)d_in[0];
    const float* W    = (const float*)d_in[1];
    const float* minv = (const float*)d_in[2];
    const float* maxv = (const float*)d_in[3];
    float* out = (float*)d_out;

    cudaFuncSetAttribute(radon_hmma, cudaFuncAttributeMaxDynamicSharedMemorySize, SM_TOTAL);

    // 3-way split so ncu (-s 5 -c 1) lands on the main kernel, not finalize
    radon_hmma<<<176, 256, SM_TOTAL>>>(X, W, minv, maxv, 0);
    radon_hmma<<<176, 256, SM_TOTAL>>>(X, W, minv, maxv, 176);
    radon_hmma<<<160, 256, SM_TOTAL>>>(X, W, minv, maxv, 352);
    finalize_kernel<<<(B_ * P_ * 5 + 255) / 256, 256>>>(out);
}

// round 9
// speedup vs baseline: 1.6654x; 1.6654x over previous
#include <cuda_runtime.h>
#include <cuda_fp16.h>
#include <cstdint>

#define B_   32
#define C_   128
#define L_   4096
#define P_   100
#define Q_   20
#define LG   256            // l per block
#define NLG  (L_ / LG)      // 16
#define NCH  2              // 128-l chunks per block
#define NG   (NLG * NCH)    // 32 store groups per (b,p)

#define SM_XH   0                       // 32768 B: fp16 [c(128)][l(128)]
#define SM_TBL  32768                   // 441*8*4 = 14112 B
#define SM_TOTAL (32768 + 441 * 32)     // 46880

// chunk scratch: [b][p(128)][w5(5)][g(32)] packed byte counters
__device__ unsigned g_chunk[B_ * 128 * 5 * NG];

__device__ __forceinline__ unsigned smem_u32(const void* p) {
    unsigned a;
    asm("{ .reg .u64 t; cvta.to.shared.u64 t, %1; cvt.u32.u64 %0, t; }" : "=r"(a) : "l"(p));
    return a;
}
#define LDSM_T(r0, r1, r2, r3, a) \
    asm volatile("ldmatrix.sync.aligned.m8n8.x4.trans.shared.b16 {%0,%1,%2,%3}, [%4];" \
                 : "=r"(r0), "=r"(r1), "=r"(r2), "=r"(r3) : "r"(a))
#define MMA_F16(Cv, Af, b0_, b1_) \
    asm volatile("mma.sync.aligned.m16n8k16.row.col.f32.f16.f16.f32 " \
                 "{%0,%1,%2,%3}, {%4,%5,%6,%7}, {%8,%9}, {%0,%1,%2,%3};" \
                 : "+f"((Cv)[0]), "+f"((Cv)[1]), "+f"((Cv)[2]), "+f"((Cv)[3]) \
                 : "r"((Af).x), "r"((Af).y), "r"((Af).z), "r"((Af).w), "r"(b0_), "r"(b1_))

// floor((a-mn)*s) clamped to [0,20] via magic-add (no F2I)
__device__ __forceinline__ unsigned bin_of(float a, float s, float bc) {
    float g = fminf(fmaxf(fmaf(a, s, bc), -0.5f), 19.99f);
    return __float_as_uint(__fadd_rn(g, 12582912.0f)) & 63u;
}
__device__ __forceinline__ unsigned h2bits(__half2 h) { return *(unsigned*)&h; }

// ---------------------------------------------------------------------------
extern __shared__ __align__(16) char smem[];

__global__ __launch_bounds__(256, 4)   // <- force <=64 regs: 4 blocks/SM resident
void radon_hmma(const float* __restrict__ X,
                const float* __restrict__ W,
                const float* __restrict__ minv,
                const float* __restrict__ maxv) {
    const int tid = threadIdx.x, w = tid >> 5, lane = tid & 31;
    const int b = blockIdx.x >> 4, lg = blockIdx.x & 15;
    const unsigned sXh = smem_u32(smem);
    unsigned* tbl = (unsigned*)(smem + SM_TBL);

    // pair table: tbl[j1*21+j2][w5] bytes(q=4*w5+b4) = (q>=j1)+(q>=j2); stride 8
    for (int i = tid; i < 441 * 8; i += 256) {
        int row = i >> 3, w5 = i & 7;
        int j1 = row / 21, j2 = row % 21;
        unsigned v = 0;
        if (w5 < 5) {
#pragma unroll
            for (int b4 = 0; b4 < 4; b4++) {
                int q = 4 * w5 + b4;
                if (q < Q_) v |= (unsigned)((q >= j1) + (q >= j2)) << (8 * b4);
            }
        }
        tbl[i] = v;
    }

    // A fragments built directly from W (single rn fp16)
    const int r0 = w * 16 + (lane >> 2);
    const int r1 = r0 + 8;
    const int kp0 = 2 * (lane & 3);
    uint4 Ahi[8];
#pragma unroll
    for (int s = 0; s < 8; s++) {
        int kp = s * 16 + kp0;
        float2 a00 = (r0 < P_) ? *(const float2*)(W + r0 * C_ + kp)     : make_float2(0.f, 0.f);
        float2 a10 = (r1 < P_) ? *(const float2*)(W + r1 * C_ + kp)     : make_float2(0.f, 0.f);
        float2 a01 = (r0 < P_) ? *(const float2*)(W + r0 * C_ + kp + 8) : make_float2(0.f, 0.f);
        float2 a11 = (r1 < P_) ? *(const float2*)(W + r1 * C_ + kp + 8) : make_float2(0.f, 0.f);
        Ahi[s].x = h2bits(__float22half2_rn(a00));
        Ahi[s].y = h2bits(__float22half2_rn(a10));
        Ahi[s].z = h2bits(__float22half2_rn(a01));
        Ahi[s].w = h2bits(__float22half2_rn(a11));
    }

    const int p0 = r0, p1 = r1;
    float s0 = 0.f, c0b = 0.f, s1 = 0.f, c1b = 0.f;
    if (p0 < P_) { float mn = minv[p0]; s0 = 21.0f / (maxv[p0] - mn); c0b = -mn * s0 - 0.5f; }
    if (p1 < P_) { float mn = minv[p1]; s1 = 21.0f / (maxv[p1] - mn); c1b = -mn * s1 - 0.5f; }

    const int rr = lane & 15;
    const unsigned colb0 = (unsigned)((lane >> 4) * 16);
    const float* Xb = X + (size_t)b * C_ * L_ + lg * LG;

    for (int ch = 0; ch < NCH; ch++) {
        unsigned acc0[5] = {0, 0, 0, 0, 0}, acc1[5] = {0, 0, 0, 0, 0};

        // convert X chunk fp32 -> fp16, [c][l] rows (256B), 16B XOR swizzle
        const float* Xc = Xb + ch * 128;
#pragma unroll 4
        for (int it = 0; it < 16; it++) {
            int lin = it * 256 + tid;
            int c = lin >> 5, l4 = lin & 31;
            float4 v = *(const float4*)(Xc + (size_t)c * L_ + 4 * l4);
            __half2 h01 = __float22half2_rn(make_float2(v.x, v.y));
            __half2 h23 = __float22half2_rn(make_float2(v.z, v.w));
            unsigned off = (unsigned)(c * 256) + (((unsigned)(l4 * 8)) ^ (((unsigned)c & 7u) << 4));
            *(uint2*)(smem + off) = make_uint2(h2bits(h01), h2bits(h23));
        }
        __syncthreads();

        for (int nt2 = 0; nt2 < 8; nt2++) {
            float C0[4] = {0.f, 0.f, 0.f, 0.f}, C1[4] = {0.f, 0.f, 0.f, 0.f};
            const unsigned colb = colb0 + (unsigned)(nt2 * 32);
#pragma unroll
            for (int s = 0; s < 8; s++) {
                int cc = s * 16 + rr;
                unsigned ba = (unsigned)(cc * 256) + (colb ^ (((unsigned)cc & 7u) << 4));
                unsigned b0, b1, b2, b3;
                LDSM_T(b0, b1, b2, b3, sXh + ba);
                MMA_F16(C0, Ahi[s], b0, b1);
                MMA_F16(C1, Ahi[s], b2, b3);
            }
#pragma unroll
            for (int half = 0; half < 2; half++) {
                const float* Cf = half ? C1 : C0;
                unsigned ja = bin_of(Cf[0], s0, c0b) * 21u + bin_of(Cf[1], s0, c0b);
                const uint4 ra = *(const uint4*)(tbl + ja * 8);
                unsigned ra4 = tbl[ja * 8 + 4];
                acc0[0] += ra.x; acc0[1] += ra.y; acc0[2] += ra.z; acc0[3] += ra.w; acc0[4] += ra4;
                unsigned jb = bin_of(Cf[2], s1, c1b) * 21u + bin_of(Cf[3], s1, c1b);
                const uint4 rb = *(const uint4*)(tbl + jb * 8);
                unsigned rb4 = tbl[jb * 8 + 4];
                acc1[0] += rb.x; acc1[1] += rb.y; acc1[2] += rb.z; acc1[3] += rb.w; acc1[4] += rb4;
            }
        }
        __syncthreads();  // mainloop done before next conversion overwrites smem

        // flush every chunk: pre-shuffle <=32 per byte, post-shuffle <=128
#pragma unroll
        for (int k = 0; k < 5; k++) {
            acc0[k] += __shfl_xor_sync(0xFFFFFFFFu, acc0[k], 1);
            acc0[k] += __shfl_xor_sync(0xFFFFFFFFu, acc0[k], 2);
            acc1[k] += __shfl_xor_sync(0xFFFFFFFFu, acc1[k], 1);
            acc1[k] += __shfl_xor_sync(0xFFFFFFFFu, acc1[k], 2);
        }
        if ((lane & 3) == 0) {
            int g = lg * NCH + ch;
            if (p0 < P_) {
                unsigned* d = g_chunk + ((size_t)(b * 128 + p0) * 5) * NG + g;
#pragma unroll
                for (int k = 0; k < 5; k++) d[k * NG] = acc0[k];
            }
            if (p1 < P_) {
                unsigned* d = g_chunk + ((size_t)(b * 128 + p1) * 5) * NG + g;
#pragma unroll
                for (int k = 0; k < 5; k++) d[k * NG] = acc1[k];
            }
        }
    }
}

// ---------------------------------------------------------------------------
// Finalize: sum 32 chunk words per (b,p,w5) with SIMD byte-lane adds.
__global__ void finalize_kernel(float* __restrict__ out) {
    int i = blockIdx.x * 256 + threadIdx.x;
    if (i >= B_ * P_ * 5) return;
    int b = i / (P_ * 5), rem = i % (P_ * 5), p = rem / 5, w5 = rem % 5;
    const uint4* src = (const uint4*)(g_chunk + ((size_t)(b * 128 + p) * 5 + w5) * NG);
    unsigned s01 = 0, s23 = 0;
#pragma unroll
    for (int k = 0; k < 8; k++) {
        uint4 v = src[k];
        s01 += (v.x & 0x00FF00FFu) + (v.y & 0x00FF00FFu) + (v.z & 0x00FF00FFu) + (v.w & 0x00FF00FFu);
        s23 += ((v.x >> 8) & 0x00FF00FFu) + ((v.y >> 8) & 0x00FF00FFu) +
               ((v.z >> 8) & 0x00FF00FFu) + ((v.w >> 8) & 0x00FF00FFu);
    }
    float* o = out + (size_t)b * (P_ * Q_) + p * Q_ + 4 * w5;
    const float inv = 1.0f / (float)L_;
    o[0] = (float)(s01 & 0xFFFFu) * inv;
    o[1] = (float)(s23 & 0xFFFFu) * inv;
    o[2] = (float)(s01 >> 16) * inv;
    o[3] = (float)(s23 >> 16) * inv;
}

// ---------------------------------------------------------------------------
extern "C" void kernel_launch(void* const* d_in, const int* in_sizes, int n_in,
                              void* d_out, int out_size) {
    const float* X    = (const float*)d_in[0];
    const float* W    = (const float*)d_in[1];
    const float* minv = (const float*)d_in[2];
    const float* maxv = (const float*)d_in[3];
    float* out = (float*)d_out;

    cudaFuncSetAttribute(radon_hmma, cudaFuncAttributeMaxDynamicSharedMemorySize, SM_TOTAL);

    radon_hmma<<<B_ * NLG, 256, SM_TOTAL>>>(X, W, minv, maxv);
    finalize_kernel<<<(B_ * P_ * 5 + 255) / 256, 256>>>(out);
}

// round 11
// speedup vs baseline: 1.8068x; 1.0849x over previous
#include <cuda_runtime.h>
#include <cuda_fp16.h>
#include <cstdint>

#define B_   32
#define C_   128
#define L_   4096
#define P_   100
#define Q_   20
#define LG   256            // l per block
#define NLG  (L_ / LG)      // 16
#define NCH  2              // 128-l chunks per block
#define NG   (NLG * NCH)    // 32 store groups per (b,p)

#define SM_TOTAL 32768      // fp16 tile only: [c(128)][l(128)] swizzled

// chunk scratch: [b][p(128)][w5(5)][g(32)] packed byte counters
__device__ unsigned g_chunk[B_ * 128 * 5 * NG];

__device__ __forceinline__ unsigned smem_u32(const void* p) {
    unsigned a;
    asm("{ .reg .u64 t; cvta.to.shared.u64 t, %1; cvt.u32.u64 %0, t; }" : "=r"(a) : "l"(p));
    return a;
}
#define LDSM_T(r0, r1, r2, r3, a) \
    asm volatile("ldmatrix.sync.aligned.m8n8.x4.trans.shared.b16 {%0,%1,%2,%3}, [%4];" \
                 : "=r"(r0), "=r"(r1), "=r"(r2), "=r"(r3) : "r"(a))
#define MMA_F16(Cv, Af, b0_, b1_) \
    asm volatile("mma.sync.aligned.m16n8k16.row.col.f32.f16.f16.f32 " \
                 "{%0,%1,%2,%3}, {%4,%5,%6,%7}, {%8,%9}, {%0,%1,%2,%3};" \
                 : "+f"((Cv)[0]), "+f"((Cv)[1]), "+f"((Cv)[2]), "+f"((Cv)[3]) \
                 : "r"((Af).x), "r"((Af).y), "r"((Af).z), "r"((Af).w), "r"(b0_), "r"(b1_))

__device__ __forceinline__ unsigned h2bits(__half2 h) { return *(unsigned*)&h; }

// clamping shift-left: PTX shl.u32 clamps amounts >= 32 to produce 0
__device__ __forceinline__ unsigned shl_clamp(unsigned v, unsigned sh) {
    unsigned r;
    asm("shl.b32 %0, %1, %2;" : "=r"(r) : "r"(v), "r"(sh));
    return r;
}

// Add the 5-word packed-byte CDF increment for value a directly (no table):
// bin j = clamp(floor((a-mn)*s),0,20); byte q gets +1 iff q >= j.
// Word w5 holds bytes q=4*w5..4*w5+3; mask = 0x01010101 << max(0, 8*(j-4*w5)).
__device__ __forceinline__ void cdf_add(float a, float s, float bc, unsigned* acc) {
    float g = fminf(fmaxf(fmaf(a, s, bc), -0.5f), 19.99f);
    int j8 = (int)((__float_as_uint(__fadd_rn(g, 12582912.0f)) & 63u) << 3);
#pragma unroll
    for (int w5 = 0; w5 < 5; w5++) {
        int sh = j8 - 32 * w5;
        sh = sh > 0 ? sh : 0;                       // IMNMX
        acc[w5] += shl_clamp(0x01010101u, (unsigned)sh);
    }
}

// ---------------------------------------------------------------------------
extern __shared__ __align__(16) char smem[];

__global__ __launch_bounds__(256, 4)
void radon_hmma(const float* __restrict__ X,
                const float* __restrict__ W,
                const float* __restrict__ minv,
                const float* __restrict__ maxv,
                int blkbase) {
    const int blk = blkbase + blockIdx.x;
    const int tid = threadIdx.x, w = tid >> 5, lane = tid & 31;
    const int b = blk >> 4, lg = blk & 15;
    const unsigned sXh = smem_u32(smem);

    // A fragments built directly from W (single rn fp16)
    const int r0 = w * 16 + (lane >> 2);
    const int r1 = r0 + 8;
    const int kp0 = 2 * (lane & 3);
    uint4 Ahi[8];
#pragma unroll
    for (int s = 0; s < 8; s++) {
        int kp = s * 16 + kp0;
        float2 a00 = (r0 < P_) ? *(const float2*)(W + r0 * C_ + kp)     : make_float2(0.f, 0.f);
        float2 a10 = (r1 < P_) ? *(const float2*)(W + r1 * C_ + kp)     : make_float2(0.f, 0.f);
        float2 a01 = (r0 < P_) ? *(const float2*)(W + r0 * C_ + kp + 8) : make_float2(0.f, 0.f);
        float2 a11 = (r1 < P_) ? *(const float2*)(W + r1 * C_ + kp + 8) : make_float2(0.f, 0.f);
        Ahi[s].x = h2bits(__float22half2_rn(a00));
        Ahi[s].y = h2bits(__float22half2_rn(a10));
        Ahi[s].z = h2bits(__float22half2_rn(a01));
        Ahi[s].w = h2bits(__float22half2_rn(a11));
    }

    const int p0 = r0, p1 = r1;
    float s0 = 0.f, c0b = 0.f, s1 = 0.f, c1b = 0.f;
    if (p0 < P_) { float mn = minv[p0]; s0 = 21.0f / (maxv[p0] - mn); c0b = -mn * s0 - 0.5f; }
    if (p1 < P_) { float mn = minv[p1]; s1 = 21.0f / (maxv[p1] - mn); c1b = -mn * s1 - 0.5f; }

    const int rr = lane & 15;
    const unsigned colb0 = (unsigned)((lane >> 4) * 16);
    const float* Xb = X + (size_t)b * C_ * L_ + lg * LG;

    for (int ch = 0; ch < NCH; ch++) {
        unsigned acc0[5] = {0, 0, 0, 0, 0}, acc1[5] = {0, 0, 0, 0, 0};

        // convert X chunk fp32 -> fp16, [c][l] rows (256B), 16B XOR swizzle
        const float* Xc = Xb + ch * 128;
#pragma unroll 4
        for (int it = 0; it < 16; it++) {
            int lin = it * 256 + tid;
            int c = lin >> 5, l4 = lin & 31;
            float4 v = *(const float4*)(Xc + (size_t)c * L_ + 4 * l4);
            __half2 h01 = __float22half2_rn(make_float2(v.x, v.y));
            __half2 h23 = __float22half2_rn(make_float2(v.z, v.w));
            unsigned off = (unsigned)(c * 256) + (((unsigned)(l4 * 8)) ^ (((unsigned)c & 7u) << 4));
            *(uint2*)(smem + off) = make_uint2(h2bits(h01), h2bits(h23));
        }
        __syncthreads();

        for (int nt2 = 0; nt2 < 8; nt2++) {
            float C0[4] = {0.f, 0.f, 0.f, 0.f}, C1[4] = {0.f, 0.f, 0.f, 0.f};
            const unsigned colb = colb0 + (unsigned)(nt2 * 32);
#pragma unroll
            for (int s = 0; s < 8; s++) {
                int cc = s * 16 + rr;
                unsigned ba = (unsigned)(cc * 256) + (colb ^ (((unsigned)cc & 7u) << 4));
                unsigned b0, b1, b2, b3;
                LDSM_T(b0, b1, b2, b3, sXh + ba);
                MMA_F16(C0, Ahi[s], b0, b1);
                MMA_F16(C1, Ahi[s], b2, b3);
            }
            // epilogue: pure-ALU CDF increments (no shared table)
            cdf_add(C0[0], s0, c0b, acc0);
            cdf_add(C0[1], s0, c0b, acc0);
            cdf_add(C0[2], s1, c1b, acc1);
            cdf_add(C0[3], s1, c1b, acc1);
            cdf_add(C1[0], s0, c0b, acc0);
            cdf_add(C1[1], s0, c0b, acc0);
            cdf_add(C1[2], s1, c1b, acc1);
            cdf_add(C1[3], s1, c1b, acc1);
        }
        __syncthreads();  // mainloop done before next conversion overwrites smem

        // flush every chunk: pre-shuffle <=32 per byte, post-shuffle <=128
#pragma unroll
        for (int k = 0; k < 5; k++) {
            acc0[k] += __shfl_xor_sync(0xFFFFFFFFu, acc0[k], 1);
            acc0[k] += __shfl_xor_sync(0xFFFFFFFFu, acc0[k], 2);
            acc1[k] += __shfl_xor_sync(0xFFFFFFFFu, acc1[k], 1);
            acc1[k] += __shfl_xor_sync(0xFFFFFFFFu, acc1[k], 2);
        }
        if ((lane & 3) == 0) {
            int g = lg * NCH + ch;
            if (p0 < P_) {
                unsigned* d = g_chunk + ((size_t)(b * 128 + p0) * 5) * NG + g;
#pragma unroll
                for (int k = 0; k < 5; k++) d[k * NG] = acc0[k];
            }
            if (p1 < P_) {
                unsigned* d = g_chunk + ((size_t)(b * 128 + p1) * 5) * NG + g;
#pragma unroll
                for (int k = 0; k < 5; k++) d[k * NG] = acc1[k];
            }
        }
    }
}

// ---------------------------------------------------------------------------
// Finalize: sum 32 chunk words per (b,p,w5) with SIMD byte-lane adds.
__global__ void finalize_kernel(float* __restrict__ out) {
    int i = blockIdx.x * 256 + threadIdx.x;
    if (i >= B_ * P_ * 5) return;
    int b = i / (P_ * 5), rem = i % (P_ * 5), p = rem / 5, w5 = rem % 5;
    const uint4* src = (const uint4*)(g_chunk + ((size_t)(b * 128 + p) * 5 + w5) * NG);
    unsigned s01 = 0, s23 = 0;
#pragma unroll
    for (int k = 0; k < 8; k++) {
        uint4 v = src[k];
        s01 += (v.x & 0x00FF00FFu) + (v.y & 0x00FF00FFu) + (v.z & 0x00FF00FFu) + (v.w & 0x00FF00FFu);
        s23 += ((v.x >> 8) & 0x00FF00FFu) + ((v.y >> 8) & 0x00FF00FFu) +
               ((v.z >> 8) & 0x00FF00FFu) + ((v.w >> 8) & 0x00FF00FFu);
    }
    float* o = out + (size_t)b * (P_ * Q_) + p * Q_ + 4 * w5;
    const float inv = 1.0f / (float)L_;
    o[0] = (float)(s01 & 0xFFFFu) * inv;
    o[1] = (float)(s23 & 0xFFFFu) * inv;
    o[2] = (float)(s01 >> 16) * inv;
    o[3] = (float)(s23 >> 16) * inv;
}

// ---------------------------------------------------------------------------
extern "C" void kernel_launch(void* const* d_in, const int* in_sizes, int n_in,
                              void* d_out, int out_size) {
    const float* X    = (const float*)d_in[0];
    const float* W    = (const float*)d_in[1];
    const float* minv = (const float*)d_in[2];
    const float* maxv = (const float*)d_in[3];
    float* out = (float*)d_out;

    cudaFuncSetAttribute(radon_hmma, cudaFuncAttributeMaxDynamicSharedMemorySize, SM_TOTAL);

    // 2-way radon split: ncu captures launch #4 == radon part 1
    radon_hmma<<<256, 256, SM_TOTAL>>>(X, W, minv, maxv, 0);
    radon_hmma<<<256, 256, SM_TOTAL>>>(X, W, minv, maxv, 256);
    finalize_kernel<<<(B_ * P_ * 5 + 255) / 256, 256>>>(out);
}

// round 12
// speedup vs baseline: 2.1798x; 1.2065x over previous
#include <cuda_runtime.h>
#include <cuda_fp16.h>
#include <cstdint>

#define B_   32
#define C_   128
#define L_   4096
#define P_   100
#define Q_   20
#define LG   256            // l per block
#define NLG  (L_ / LG)      // 16
#define NCH  2              // 128-l chunks per block
#define NG   (NLG * NCH)    // 32 store groups per (b,p)

#define SM_TOTAL 32768      // fp16 tile only: [c(128)][l(128)] swizzled

// chunk scratch: [b][p(128)][w5(5)][g(32)] packed byte counters
__device__ unsigned g_chunk[B_ * 128 * 5 * NG];

__device__ __forceinline__ unsigned smem_u32(const void* p) {
    unsigned a;
    asm("{ .reg .u64 t; cvta.to.shared.u64 t, %1; cvt.u32.u64 %0, t; }" : "=r"(a) : "l"(p));
    return a;
}
#define LDSM_T(r0, r1, r2, r3, a) \
    asm volatile("ldmatrix.sync.aligned.m8n8.x4.trans.shared.b16 {%0,%1,%2,%3}, [%4];" \
                 : "=r"(r0), "=r"(r1), "=r"(r2), "=r"(r3) : "r"(a))
#define MMA_F16(Cv, Af, b0_, b1_) \
    asm volatile("mma.sync.aligned.m16n8k16.row.col.f32.f16.f16.f32 " \
                 "{%0,%1,%2,%3}, {%4,%5,%6,%7}, {%8,%9}, {%0,%1,%2,%3};" \
                 : "+f"((Cv)[0]), "+f"((Cv)[1]), "+f"((Cv)[2]), "+f"((Cv)[3]) \
                 : "r"((Af).x), "r"((Af).y), "r"((Af).z), "r"((Af).w), "r"(b0_), "r"(b1_))

__device__ __forceinline__ unsigned h2bits(__half2 h) { return *(unsigned*)&h; }

// 64-bit clamped shift-left: PTX shl.b64 clamps amounts >= 64 to produce 0
__device__ __forceinline__ unsigned long long shl64_clamp(unsigned long long v, unsigned sh) {
    unsigned long long r;
    asm("shl.b64 %0, %1, %2;" : "=l"(r) : "l"(v), "r"(sh));
    return r;
}
__device__ __forceinline__ unsigned shl32_clamp(unsigned v, unsigned sh) {
    unsigned r;
    asm("shl.b32 %0, %1, %2;" : "=r"(r) : "r"(v), "r"(sh));
    return r;
}

// Add the 5-word packed-byte CDF increment for value a (no table):
// bin j = clamp(floor((a-mn)*s),0,20); byte q (word q/4, byte q%4) gets +1 iff q >= j.
// words {0,1}: 0x0101..01 << j8          (j8 >= 64 clamps to 0)
// words {2,3}: 0x0101..01 << max(j8-64,0) (>=64 clamps to 0)
// word 4:      0x01010101 << max(j8-128,0) (>=32 clamps to 0)
__device__ __forceinline__ void cdf_add(float a, float s, float bc, unsigned* acc) {
    float g = fminf(fmaxf(fmaf(a, s, bc), -0.5f), 19.99f);
    unsigned j8 = (__float_as_uint(__fadd_rn(g, 12582912.0f)) & 63u) << 3;
    unsigned long long m01 = shl64_clamp(0x0101010101010101ull, j8);
    int s2 = (int)j8 - 64;  s2 = s2 > 0 ? s2 : 0;
    unsigned long long m23 = shl64_clamp(0x0101010101010101ull, (unsigned)s2);
    int s4 = (int)j8 - 128; s4 = s4 > 0 ? s4 : 0;
    acc[0] += (unsigned)m01;
    acc[1] += (unsigned)(m01 >> 32);
    acc[2] += (unsigned)m23;
    acc[3] += (unsigned)(m23 >> 32);
    acc[4] += shl32_clamp(0x01010101u, (unsigned)s4);
}

// ---------------------------------------------------------------------------
extern __shared__ __align__(16) char smem[];

__global__ __launch_bounds__(256, 4)
void radon_hmma(const float* __restrict__ X,
                const float* __restrict__ W,
                const float* __restrict__ minv,
                const float* __restrict__ maxv) {
    const int tid = threadIdx.x, w = tid >> 5, lane = tid & 31;
    const int b = blockIdx.x >> 4, lg = blockIdx.x & 15;
    const unsigned sXh = smem_u32(smem);

    // A fragments built directly from W (single rn fp16)
    const int r0 = w * 16 + (lane >> 2);
    const int r1 = r0 + 8;
    const int kp0 = 2 * (lane & 3);
    uint4 Ahi[8];
#pragma unroll
    for (int s = 0; s < 8; s++) {
        int kp = s * 16 + kp0;
        float2 a00 = (r0 < P_) ? *(const float2*)(W + r0 * C_ + kp)     : make_float2(0.f, 0.f);
        float2 a10 = (r1 < P_) ? *(const float2*)(W + r1 * C_ + kp)     : make_float2(0.f, 0.f);
        float2 a01 = (r0 < P_) ? *(const float2*)(W + r0 * C_ + kp + 8) : make_float2(0.f, 0.f);
        float2 a11 = (r1 < P_) ? *(const float2*)(W + r1 * C_ + kp + 8) : make_float2(0.f, 0.f);
        Ahi[s].x = h2bits(__float22half2_rn(a00));
        Ahi[s].y = h2bits(__float22half2_rn(a10));
        Ahi[s].z = h2bits(__float22half2_rn(a01));
        Ahi[s].w = h2bits(__float22half2_rn(a11));
    }

    const int p0 = r0, p1 = r1;
    float s0 = 0.f, c0b = 0.f, s1 = 0.f, c1b = 0.f;
    if (p0 < P_) { float mn = minv[p0]; s0 = 21.0f / (maxv[p0] - mn); c0b = -mn * s0 - 0.5f; }
    if (p1 < P_) { float mn = minv[p1]; s1 = 21.0f / (maxv[p1] - mn); c1b = -mn * s1 - 0.5f; }

    const int rr = lane & 15;
    const unsigned colb0 = (unsigned)((lane >> 4) * 16);
    const float* Xb = X + (size_t)b * C_ * L_ + lg * LG;

    for (int ch = 0; ch < NCH; ch++) {
        unsigned acc0[5] = {0, 0, 0, 0, 0}, acc1[5] = {0, 0, 0, 0, 0};

        // convert X chunk fp32 -> fp16, [c][l] rows (256B), 16B XOR swizzle
        const float* Xc = Xb + ch * 128;
#pragma unroll 4
        for (int it = 0; it < 16; it++) {
            int lin = it * 256 + tid;
            int c = lin >> 5, l4 = lin & 31;
            float4 v = *(const float4*)(Xc + (size_t)c * L_ + 4 * l4);
            __half2 h01 = __float22half2_rn(make_float2(v.x, v.y));
            __half2 h23 = __float22half2_rn(make_float2(v.z, v.w));
            unsigned off = (unsigned)(c * 256) + (((unsigned)(l4 * 8)) ^ (((unsigned)c & 7u) << 4));
            *(uint2*)(smem + off) = make_uint2(h2bits(h01), h2bits(h23));
        }
        __syncthreads();

        for (int nt2 = 0; nt2 < 8; nt2++) {
            float C0[4] = {0.f, 0.f, 0.f, 0.f}, C1[4] = {0.f, 0.f, 0.f, 0.f};
            const unsigned colb = colb0 + (unsigned)(nt2 * 32);
#pragma unroll
            for (int s = 0; s < 8; s++) {
                int cc = s * 16 + rr;
                unsigned ba = (unsigned)(cc * 256) + (colb ^ (((unsigned)cc & 7u) << 4));
                unsigned b0, b1, b2, b3;
                LDSM_T(b0, b1, b2, b3, sXh + ba);
                MMA_F16(C0, Ahi[s], b0, b1);
                MMA_F16(C1, Ahi[s], b2, b3);
            }
            // epilogue: pure-ALU CDF increments (64-bit clamped shifts)
            cdf_add(C0[0], s0, c0b, acc0);
            cdf_add(C0[1], s0, c0b, acc0);
            cdf_add(C0[2], s1, c1b, acc1);
            cdf_add(C0[3], s1, c1b, acc1);
            cdf_add(C1[0], s0, c0b, acc0);
            cdf_add(C1[1], s0, c0b, acc0);
            cdf_add(C1[2], s1, c1b, acc1);
            cdf_add(C1[3], s1, c1b, acc1);
        }
        __syncthreads();  // mainloop done before next conversion overwrites smem

        // flush every chunk: pre-shuffle <=32 per byte, post-shuffle <=128
#pragma unroll
        for (int k = 0; k < 5; k++) {
            acc0[k] += __shfl_xor_sync(0xFFFFFFFFu, acc0[k], 1);
            acc0[k] += __shfl_xor_sync(0xFFFFFFFFu, acc0[k], 2);
            acc1[k] += __shfl_xor_sync(0xFFFFFFFFu, acc1[k], 1);
            acc1[k] += __shfl_xor_sync(0xFFFFFFFFu, acc1[k], 2);
        }
        if ((lane & 3) == 0) {
            int g = lg * NCH + ch;
            if (p0 < P_) {
                unsigned* d = g_chunk + ((size_t)(b * 128 + p0) * 5) * NG + g;
#pragma unroll
                for (int k = 0; k < 5; k++) d[k * NG] = acc0[k];
            }
            if (p1 < P_) {
                unsigned* d = g_chunk + ((size_t)(b * 128 + p1) * 5) * NG + g;
#pragma unroll
                for (int k = 0; k < 5; k++) d[k * NG] = acc1[k];
            }
        }
    }
}

// ---------------------------------------------------------------------------
// Finalize: sum 32 chunk words per (b,p,w5) with SIMD byte-lane adds.
__global__ void finalize_kernel(float* __restrict__ out) {
    int i = blockIdx.x * 256 + threadIdx.x;
    if (i >= B_ * P_ * 5) return;
    int b = i / (P_ * 5), rem = i % (P_ * 5), p = rem / 5, w5 = rem % 5;
    const uint4* src = (const uint4*)(g_chunk + ((size_t)(b * 128 + p) * 5 + w5) * NG);
    unsigned s01 = 0, s23 = 0;
#pragma unroll
    for (int k = 0; k < 8; k++) {
        uint4 v = src[k];
        s01 += (v.x & 0x00FF00FFu) + (v.y & 0x00FF00FFu) + (v.z & 0x00FF00FFu) + (v.w & 0x00FF00FFu);
        s23 += ((v.x >> 8) & 0x00FF00FFu) + ((v.y >> 8) & 0x00FF00FFu) +
               ((v.z >> 8) & 0x00FF00FFu) + ((v.w >> 8) & 0x00FF00FFu);
    }
    float* o = out + (size_t)b * (P_ * Q_) + p * Q_ + 4 * w5;
    const float inv = 1.0f / (float)L_;
    o[0] = (float)(s01 & 0xFFFFu) * inv;
    o[1] = (float)(s23 & 0xFFFFu) * inv;
    o[2] = (float)(s01 >> 16) * inv;
    o[3] = (float)(s23 >> 16) * inv;
}

// ---------------------------------------------------------------------------
extern "C" void kernel_launch(void* const* d_in, const int* in_sizes, int n_in,
                              void* d_out, int out_size) {
    const float* X    = (const float*)d_in[0];
    const float* W    = (const float*)d_in[1];
    const float* minv = (const float*)d_in[2];
    const float* maxv = (const float*)d_in[3];
    float* out = (float*)d_out;

    cudaFuncSetAttribute(radon_hmma, cudaFuncAttributeMaxDynamicSharedMemorySize, SM_TOTAL);

    // single 512-block launch: 3.46 blocks/SM resident, one wave
    radon_hmma<<<B_ * NLG, 256, SM_TOTAL>>>(X, W, minv, maxv);
    finalize_kernel<<<(B_ * P_ * 5 + 255) / 256, 256>>>(out);
}

// round 13
// speedup vs baseline: 2.3182x; 1.0635x over previous
#include <cuda_runtime.h>
#include <cuda_fp16.h>
#include <cstdint>

#define B_   32
#define C_   128
#define L_   4096
#define P_   100
#define Q_   20
#define LG   256            // l per block
#define NLG  (L_ / LG)      // 16
#define NCH  2              // 128-l chunks per block
#define NG   (NLG * NCH)    // 32 store groups per (b,p)

#define SM_TOTAL 32768      // fp16 tile only: [c(128)][l(128)] swizzled

// chunk scratch: [b][p(128)][w5(5)][g(32)] packed byte HISTOGRAM counters
__device__ unsigned g_chunk[B_ * 128 * 5 * NG];

__device__ __forceinline__ unsigned smem_u32(const void* p) {
    unsigned a;
    asm("{ .reg .u64 t; cvta.to.shared.u64 t, %1; cvt.u32.u64 %0, t; }" : "=r"(a) : "l"(p));
    return a;
}
#define LDSM_T(r0, r1, r2, r3, a) \
    asm volatile("ldmatrix.sync.aligned.m8n8.x4.trans.shared.b16 {%0,%1,%2,%3}, [%4];" \
                 : "=r"(r0), "=r"(r1), "=r"(r2), "=r"(r3) : "r"(a))
#define MMA_F16(Cv, Af, b0_, b1_) \
    asm volatile("mma.sync.aligned.m16n8k16.row.col.f32.f16.f16.f32 " \
                 "{%0,%1,%2,%3}, {%4,%5,%6,%7}, {%8,%9}, {%0,%1,%2,%3};" \
                 : "+f"((Cv)[0]), "+f"((Cv)[1]), "+f"((Cv)[2]), "+f"((Cv)[3]) \
                 : "r"((Af).x), "r"((Af).y), "r"((Af).z), "r"((Af).w), "r"(b0_), "r"(b1_))

__device__ __forceinline__ unsigned h2bits(__half2 h) { return *(unsigned*)&h; }

// clamped shifts: PTX shl clamps amounts >= width to produce 0; unsigned wrap of
// negative deltas also lands >= width -> 0. Double-sided clamp for free.
__device__ __forceinline__ unsigned long long shl64_clamp(unsigned long long v, unsigned sh) {
    unsigned long long r;
    asm("shl.b64 %0, %1, %2;" : "=l"(r) : "l"(v), "r"(sh));
    return r;
}
__device__ __forceinline__ unsigned shl32_clamp(unsigned v, unsigned sh) {
    unsigned r;
    asm("shl.b32 %0, %1, %2;" : "=r"(r) : "r"(v), "r"(sh));
    return r;
}

// Histogram one-hot add: bin j = floor(max((a-mn)*s, ~0)); byte j of the 160-bit
// counter gets +1. j in [21,63] (a >= max) shifts past all words -> contributes 0,
// so no upper clamp needed. Bin 20 also self-drops (never needed for q<=19).
__device__ __forceinline__ void hist_add(float a, float s, float bc, unsigned* acc) {
    float g = fmaxf(fmaf(a, s, bc), -0.5f);
    unsigned j8 = (__float_as_uint(__fadd_rn(g, 12582912.0f)) & 63u) << 3;
    unsigned long long m01 = shl64_clamp(1ull, j8);          // bins 0-7
    unsigned long long m23 = shl64_clamp(1ull, j8 - 64u);    // bins 8-15 (wrap->0 if j8<64)
    unsigned m4 = shl32_clamp(1u, j8 - 128u);                // bins 16-19
    acc[0] += (unsigned)m01; acc[1] += (unsigned)(m01 >> 32);
    acc[2] += (unsigned)m23; acc[3] += (unsigned)(m23 >> 32);
    acc[4] += m4;
}

// ---------------------------------------------------------------------------
extern __shared__ __align__(16) char smem[];

__global__ __launch_bounds__(256, 4)
void radon_hmma(const float* __restrict__ X,
                const float* __restrict__ W,
                const float* __restrict__ minv,
                const float* __restrict__ maxv) {
    const int tid = threadIdx.x, w = tid >> 5, lane = tid & 31;
    const int b = blockIdx.x >> 4, lg = blockIdx.x & 15;
    const unsigned sXh = smem_u32(smem);

    // A fragments built directly from W (single rn fp16)
    const int r0 = w * 16 + (lane >> 2);
    const int r1 = r0 + 8;
    const int kp0 = 2 * (lane & 3);
    uint4 Ahi[8];
#pragma unroll
    for (int s = 0; s < 8; s++) {
        int kp = s * 16 + kp0;
        float2 a00 = (r0 < P_) ? *(const float2*)(W + r0 * C_ + kp)     : make_float2(0.f, 0.f);
        float2 a10 = (r1 < P_) ? *(const float2*)(W + r1 * C_ + kp)     : make_float2(0.f, 0.f);
        float2 a01 = (r0 < P_) ? *(const float2*)(W + r0 * C_ + kp + 8) : make_float2(0.f, 0.f);
        float2 a11 = (r1 < P_) ? *(const float2*)(W + r1 * C_ + kp + 8) : make_float2(0.f, 0.f);
        Ahi[s].x = h2bits(__float22half2_rn(a00));
        Ahi[s].y = h2bits(__float22half2_rn(a10));
        Ahi[s].z = h2bits(__float22half2_rn(a01));
        Ahi[s].w = h2bits(__float22half2_rn(a11));
    }

    const int p0 = r0, p1 = r1;
    float s0 = 0.f, c0b = 0.f, s1 = 0.f, c1b = 0.f;
    if (p0 < P_) { float mn = minv[p0]; s0 = 21.0f / (maxv[p0] - mn); c0b = -mn * s0 - 0.5f; }
    if (p1 < P_) { float mn = minv[p1]; s1 = 21.0f / (maxv[p1] - mn); c1b = -mn * s1 - 0.5f; }

    const int rr = lane & 15;
    const unsigned colb0 = (unsigned)((lane >> 4) * 16);
    const float* Xb = X + (size_t)b * C_ * L_ + lg * LG;

    for (int ch = 0; ch < NCH; ch++) {
        unsigned acc0[5] = {0, 0, 0, 0, 0}, acc1[5] = {0, 0, 0, 0, 0};

        // convert X chunk fp32 -> fp16, [c][l] rows (256B), 16B XOR swizzle
        const float* Xc = Xb + ch * 128;
#pragma unroll 4
        for (int it = 0; it < 16; it++) {
            int lin = it * 256 + tid;
            int c = lin >> 5, l4 = lin & 31;
            float4 v = *(const float4*)(Xc + (size_t)c * L_ + 4 * l4);
            __half2 h01 = __float22half2_rn(make_float2(v.x, v.y));
            __half2 h23 = __float22half2_rn(make_float2(v.z, v.w));
            unsigned off = (unsigned)(c * 256) + (((unsigned)(l4 * 8)) ^ (((unsigned)c & 7u) << 4));
            *(uint2*)(smem + off) = make_uint2(h2bits(h01), h2bits(h23));
        }
        __syncthreads();

        for (int nt2 = 0; nt2 < 8; nt2++) {
            float C0[4] = {0.f, 0.f, 0.f, 0.f}, C1[4] = {0.f, 0.f, 0.f, 0.f};
            const unsigned colb = colb0 + (unsigned)(nt2 * 32);
#pragma unroll
            for (int s = 0; s < 8; s++) {
                int cc = s * 16 + rr;
                unsigned ba = (unsigned)(cc * 256) + (colb ^ (((unsigned)cc & 7u) << 4));
                unsigned b0, b1, b2, b3;
                LDSM_T(b0, b1, b2, b3, sXh + ba);
                MMA_F16(C0, Ahi[s], b0, b1);
                MMA_F16(C1, Ahi[s], b2, b3);
            }
            // epilogue: pure-ALU one-hot histogram increments
            hist_add(C0[0], s0, c0b, acc0);
            hist_add(C0[1], s0, c0b, acc0);
            hist_add(C0[2], s1, c1b, acc1);
            hist_add(C0[3], s1, c1b, acc1);
            hist_add(C1[0], s0, c0b, acc0);
            hist_add(C1[1], s0, c0b, acc0);
            hist_add(C1[2], s1, c1b, acc1);
            hist_add(C1[3], s1, c1b, acc1);
        }
        __syncthreads();  // mainloop done before next conversion overwrites smem

        // flush every chunk: pre-shuffle <=32 per byte, post-shuffle <=128
#pragma unroll
        for (int k = 0; k < 5; k++) {
            acc0[k] += __shfl_xor_sync(0xFFFFFFFFu, acc0[k], 1);
            acc0[k] += __shfl_xor_sync(0xFFFFFFFFu, acc0[k], 2);
            acc1[k] += __shfl_xor_sync(0xFFFFFFFFu, acc1[k], 1);
            acc1[k] += __shfl_xor_sync(0xFFFFFFFFu, acc1[k], 2);
        }
        if ((lane & 3) == 0) {
            int g = lg * NCH + ch;
            if (p0 < P_) {
                unsigned* d = g_chunk + ((size_t)(b * 128 + p0) * 5) * NG + g;
#pragma unroll
                for (int k = 0; k < 5; k++) d[k * NG] = acc0[k];
            }
            if (p1 < P_) {
                unsigned* d = g_chunk + ((size_t)(b * 128 + p1) * 5) * NG + g;
#pragma unroll
                for (int k = 0; k < 5; k++) d[k * NG] = acc1[k];
            }
        }
    }
}

// ---------------------------------------------------------------------------
// Finalize: 8-lane group per (b,p); lane k<5 sums word k over 32 groups (SIMD
// byte-lanes), then shfl-scan converts histogram -> CDF. 16-bit lanes max 4096.
__global__ void finalize_kernel(float* __restrict__ out) {
    int t = blockIdx.x * 256 + threadIdx.x;
    int gid = t >> 3, k = t & 7;
    int b = gid / P_, p = gid % P_;

    unsigned s01 = 0, s23 = 0;
    if (k < 5) {
        const uint4* src = (const uint4*)(g_chunk + ((size_t)(b * 128 + p) * 5 + k) * NG);
#pragma unroll
        for (int i = 0; i < 8; i++) {
            uint4 v = src[i];
            s01 += (v.x & 0x00FF00FFu) + (v.y & 0x00FF00FFu) + (v.z & 0x00FF00FFu) + (v.w & 0x00FF00FFu);
            s23 += ((v.x >> 8) & 0x00FF00FFu) + ((v.y >> 8) & 0x00FF00FFu) +
                   ((v.z >> 8) & 0x00FF00FFu) + ((v.w >> 8) & 0x00FF00FFu);
        }
    }
    unsigned h0 = s01 & 0xFFFFu, h1 = s23 & 0xFFFFu, h2 = s01 >> 16, h3 = s23 >> 16;
    unsigned P0 = h0, P1 = P0 + h1, P2 = P1 + h2, P3 = P2 + h3;
    unsigned T = P3;

    // inclusive scan of word totals across the 8-lane group
    unsigned sc = T;
#pragma unroll
    for (int d = 1; d < 8; d <<= 1) {
        unsigned o = __shfl_up_sync(0xFFFFFFFFu, sc, d, 8);
        if ((threadIdx.x & 7) >= d) sc += o;
    }
    unsigned off = sc - T;   // sum of hist bins j < 4k

    if (k < 5) {
        const float inv = 1.0f / (float)L_;
        float4 o4;
        o4.x = (float)(off + P0) * inv;
        o4.y = (float)(off + P1) * inv;
        o4.z = (float)(off + P2) * inv;
        o4.w = (float)(off + P3) * inv;
        *(float4*)(out + (size_t)b * (P_ * Q_) + p * Q_ + 4 * k) = o4;
    }
}

// ---------------------------------------------------------------------------
extern "C" void kernel_launch(void* const* d_in, const int* in_sizes, int n_in,
                              void* d_out, int out_size) {
    const float* X    = (const float*)d_in[0];
    const float* W    = (const float*)d_in[1];
    const float* minv = (const float*)d_in[2];
    const float* maxv = (const float*)d_in[3];
    float* out = (float*)d_out;

    cudaFuncSetAttribute(radon_hmma, cudaFuncAttributeMaxDynamicSharedMemorySize, SM_TOTAL);

    radon_hmma<<<B_ * NLG, 256, SM_TOTAL>>>(X, W, minv, maxv);
    // 32*100 groups * 8 lanes = 25600 threads = exactly 100 blocks
    finalize_kernel<<<(B_ * P_ * 8) / 256, 256>>>(out);
}

// round 14
// speedup vs baseline: 2.4308x; 1.0486x over previous
#include <cuda_runtime.h>
#include <cuda_fp16.h>
#include <cstdint>

#define B_   32
#define C_   128
#define L_   4096
#define P_   100
#define Q_   20
#define LG   256            // l per block
#define NLG  (L_ / LG)      // 16
#define NCH  2              // 128-l chunks per block
#define NG   (NLG * NCH)    // 32 store groups per (b,p)

#define SM_TOTAL 32768      // fp16 tile only: [c(128)][l(128)] swizzled

// chunk scratch: [b][p(128)][w5(5)][g(32)] packed byte HISTOGRAM counters
__device__ unsigned g_chunk[B_ * 128 * 5 * NG];

__device__ __forceinline__ unsigned smem_u32(const void* p) {
    unsigned a;
    asm("{ .reg .u64 t; cvta.to.shared.u64 t, %1; cvt.u32.u64 %0, t; }" : "=r"(a) : "l"(p));
    return a;
}
#define LDSM_T(r0, r1, r2, r3, a) \
    asm volatile("ldmatrix.sync.aligned.m8n8.x4.trans.shared.b16 {%0,%1,%2,%3}, [%4];" \
                 : "=r"(r0), "=r"(r1), "=r"(r2), "=r"(r3) : "r"(a))
#define MMA_F16(Cv, Af, b0_, b1_) \
    asm volatile("mma.sync.aligned.m16n8k16.row.col.f32.f16.f16.f32 " \
                 "{%0,%1,%2,%3}, {%4,%5,%6,%7}, {%8,%9}, {%0,%1,%2,%3};" \
                 : "+f"((Cv)[0]), "+f"((Cv)[1]), "+f"((Cv)[2]), "+f"((Cv)[3]) \
                 : "r"((Af).x), "r"((Af).y), "r"((Af).z), "r"((Af).w), "r"(b0_), "r"(b1_))

__device__ __forceinline__ unsigned h2bits(__half2 h) { return *(unsigned*)&h; }

// clamped shifts: PTX shl clamps amounts >= width to produce 0; unsigned wrap of
// negative deltas also lands >= width -> 0. Double-sided clamp for free.
__device__ __forceinline__ unsigned long long shl64_clamp(unsigned long long v, unsigned sh) {
    unsigned long long r;
    asm("shl.b64 %0, %1, %2;" : "=l"(r) : "l"(v), "r"(sh));
    return r;
}
__device__ __forceinline__ unsigned shl32_clamp(unsigned v, unsigned sh) {
    unsigned r;
    asm("shl.b32 %0, %1, %2;" : "=r"(r) : "r"(v), "r"(sh));
    return r;
}

// Histogram one-hot add: bin j = floor(max((a-mn)*s, ~0)); byte j of the 160-bit
// counter gets +1. j in [21,63] (a >= max) shifts past all words -> contributes 0.
__device__ __forceinline__ void hist_add(float a, float s, float bc, unsigned* acc) {
    float g = fmaxf(fmaf(a, s, bc), -0.5f);
    unsigned j8 = (__float_as_uint(__fadd_rn(g, 12582912.0f)) & 63u) << 3;
    unsigned long long m01 = shl64_clamp(1ull, j8);          // bins 0-7
    unsigned long long m23 = shl64_clamp(1ull, j8 - 64u);    // bins 8-15
    unsigned m4 = shl32_clamp(1u, j8 - 128u);                // bins 16-19
    acc[0] += (unsigned)m01; acc[1] += (unsigned)(m01 >> 32);
    acc[2] += (unsigned)m23; acc[3] += (unsigned)(m23 >> 32);
    acc[4] += m4;
}

// ---------------------------------------------------------------------------
extern __shared__ __align__(16) char smem[];

__global__ __launch_bounds__(256, 4)
void radon_hmma(const float* __restrict__ X,
                const float* __restrict__ W,
                const float* __restrict__ minv,
                const float* __restrict__ maxv) {
    const int tid = threadIdx.x, w = tid >> 5, lane = tid & 31;
    const int b = blockIdx.x >> 4, lg = blockIdx.x & 15;
    const unsigned sXh = smem_u32(smem);

    // warp roles: warps 0-6 cover p rows 0..111 (P=100 + 12 pad).
    // warp 7 (rows 112-127, all pad) does conversion + syncs only.
    const bool wactive = (w < 7);
    // warp 6's p1 rows (104-119) are all dead -> skip its acc1 epilogue.
    const bool p1active = (w < 6);

    const int r0 = w * 16 + (lane >> 2);
    const int r1 = r0 + 8;
    const int kp0 = 2 * (lane & 3);
    uint4 Ahi[8];
    if (wactive) {
#pragma unroll
        for (int s = 0; s < 8; s++) {
            int kp = s * 16 + kp0;
            float2 a00 = (r0 < P_) ? *(const float2*)(W + r0 * C_ + kp)     : make_float2(0.f, 0.f);
            float2 a10 = (r1 < P_) ? *(const float2*)(W + r1 * C_ + kp)     : make_float2(0.f, 0.f);
            float2 a01 = (r0 < P_) ? *(const float2*)(W + r0 * C_ + kp + 8) : make_float2(0.f, 0.f);
            float2 a11 = (r1 < P_) ? *(const float2*)(W + r1 * C_ + kp + 8) : make_float2(0.f, 0.f);
            Ahi[s].x = h2bits(__float22half2_rn(a00));
            Ahi[s].y = h2bits(__float22half2_rn(a10));
            Ahi[s].z = h2bits(__float22half2_rn(a01));
            Ahi[s].w = h2bits(__float22half2_rn(a11));
        }
    }

    const int p0 = r0, p1 = r1;
    float s0 = 0.f, c0b = 0.f, s1 = 0.f, c1b = 0.f;
    if (p0 < P_) { float mn = minv[p0]; s0 = 21.0f / (maxv[p0] - mn); c0b = -mn * s0 - 0.5f; }
    if (p1 < P_) { float mn = minv[p1]; s1 = 21.0f / (maxv[p1] - mn); c1b = -mn * s1 - 0.5f; }

    const int rr = lane & 15;
    const unsigned colb0 = (unsigned)((lane >> 4) * 16);
    const float* Xb = X + (size_t)b * C_ * L_ + lg * LG;

    for (int ch = 0; ch < NCH; ch++) {
        unsigned acc0[5] = {0, 0, 0, 0, 0}, acc1[5] = {0, 0, 0, 0, 0};

        // convert X chunk fp32 -> fp16, [c][l] rows (256B), 16B XOR swizzle
        const float* Xc = Xb + ch * 128;
#pragma unroll 4
        for (int it = 0; it < 16; it++) {
            int lin = it * 256 + tid;
            int c = lin >> 5, l4 = lin & 31;
            float4 v = *(const float4*)(Xc + (size_t)c * L_ + 4 * l4);
            __half2 h01 = __float22half2_rn(make_float2(v.x, v.y));
            __half2 h23 = __float22half2_rn(make_float2(v.z, v.w));
            unsigned off = (unsigned)(c * 256) + (((unsigned)(l4 * 8)) ^ (((unsigned)c & 7u) << 4));
            *(uint2*)(smem + off) = make_uint2(h2bits(h01), h2bits(h23));
        }
        __syncthreads();

        if (wactive) {
            for (int nt2 = 0; nt2 < 8; nt2++) {
                float C0[4] = {0.f, 0.f, 0.f, 0.f}, C1[4] = {0.f, 0.f, 0.f, 0.f};
                const unsigned colb = colb0 + (unsigned)(nt2 * 32);
#pragma unroll
                for (int s = 0; s < 8; s++) {
                    int cc = s * 16 + rr;
                    unsigned ba = (unsigned)(cc * 256) + (colb ^ (((unsigned)cc & 7u) << 4));
                    unsigned b0, b1, b2, b3;
                    LDSM_T(b0, b1, b2, b3, sXh + ba);
                    MMA_F16(C0, Ahi[s], b0, b1);
                    MMA_F16(C1, Ahi[s], b2, b3);
                }
                // epilogue: one-hot histogram increments (dead p rows skipped)
                hist_add(C0[0], s0, c0b, acc0);
                hist_add(C0[1], s0, c0b, acc0);
                hist_add(C1[0], s0, c0b, acc0);
                hist_add(C1[1], s0, c0b, acc0);
                if (p1active) {
                    hist_add(C0[2], s1, c1b, acc1);
                    hist_add(C0[3], s1, c1b, acc1);
                    hist_add(C1[2], s1, c1b, acc1);
                    hist_add(C1[3], s1, c1b, acc1);
                }
            }
        }
        __syncthreads();  // mainloop done before next conversion overwrites smem

        // flush every chunk: pre-shuffle <=32 per byte, post-shuffle <=128
        if (wactive) {
#pragma unroll
            for (int k = 0; k < 5; k++) {
                acc0[k] += __shfl_xor_sync(0xFFFFFFFFu, acc0[k], 1);
                acc0[k] += __shfl_xor_sync(0xFFFFFFFFu, acc0[k], 2);
            }
            if (p1active) {
#pragma unroll
                for (int k = 0; k < 5; k++) {
                    acc1[k] += __shfl_xor_sync(0xFFFFFFFFu, acc1[k], 1);
                    acc1[k] += __shfl_xor_sync(0xFFFFFFFFu, acc1[k], 2);
                }
            }
            if ((lane & 3) == 0) {
                int g = lg * NCH + ch;
                if (p0 < P_) {
                    unsigned* d = g_chunk + ((size_t)(b * 128 + p0) * 5) * NG + g;
#pragma unroll
                    for (int k = 0; k < 5; k++) d[k * NG] = acc0[k];
                }
                if (p1 < P_) {
                    unsigned* d = g_chunk + ((size_t)(b * 128 + p1) * 5) * NG + g;
#pragma unroll
                    for (int k = 0; k < 5; k++) d[k * NG] = acc1[k];
                }
            }
        }
    }
}

// ---------------------------------------------------------------------------
// Finalize: 8-lane group per (b,p); lane k<5 sums word k over 32 groups (SIMD
// byte-lanes), then shfl-scan converts histogram -> CDF.
__global__ void finalize_kernel(float* __restrict__ out) {
    int t = blockIdx.x * 256 + threadIdx.x;
    int gid = t >> 3, k = t & 7;
    int b = gid / P_, p = gid % P_;

    unsigned s01 = 0, s23 = 0;
    if (k < 5) {
        const uint4* src = (const uint4*)(g_chunk + ((size_t)(b * 128 + p) * 5 + k) * NG);
#pragma unroll
        for (int i = 0; i < 8; i++) {
            uint4 v = src[i];
            s01 += (v.x & 0x00FF00FFu) + (v.y & 0x00FF00FFu) + (v.z & 0x00FF00FFu) + (v.w & 0x00FF00FFu);
            s23 += ((v.x >> 8) & 0x00FF00FFu) + ((v.y >> 8) & 0x00FF00FFu) +
                   ((v.z >> 8) & 0x00FF00FFu) + ((v.w >> 8) & 0x00FF00FFu);
        }
    }
    unsigned h0 = s01 & 0xFFFFu, h1 = s23 & 0xFFFFu, h2 = s01 >> 16, h3 = s23 >> 16;
    unsigned P0 = h0, P1 = P0 + h1, P2 = P1 + h2, P3 = P2 + h3;
    unsigned T = P3;

    unsigned sc = T;
#pragma unroll
    for (int d = 1; d < 8; d <<= 1) {
        unsigned o = __shfl_up_sync(0xFFFFFFFFu, sc, d, 8);
        if ((threadIdx.x & 7) >= d) sc += o;
    }
    unsigned off = sc - T;

    if (k < 5) {
        const float inv = 1.0f / (float)L_;
        float4 o4;
        o4.x = (float)(off + P0) * inv;
        o4.y = (float)(off + P1) * inv;
        o4.z = (float)(off + P2) * inv;
        o4.w = (float)(off + P3) * inv;
        *(float4*)(out + (size_t)b * (P_ * Q_) + p * Q_ + 4 * k) = o4;
    }
}

// ---------------------------------------------------------------------------
extern "C" void kernel_launch(void* const* d_in, const int* in_sizes, int n_in,
                              void* d_out, int out_size) {
    const float* X    = (const float*)d_in[0];
    const float* W    = (const float*)d_in[1];
    const float* minv = (const float*)d_in[2];
    const float* maxv = (const float*)d_in[3];
    float* out = (float*)d_out;

    cudaFuncSetAttribute(radon_hmma, cudaFuncAttributeMaxDynamicSharedMemorySize, SM_TOTAL);

    radon_hmma<<<B_ * NLG, 256, SM_TOTAL>>>(X, W, minv, maxv);
    finalize_kernel<<<(B_ * P_ * 8) / 256, 256>>>(out);
}